// round 16
// baseline (speedup 1.0000x reference)
#include <cuda_runtime.h>
#include <cuda_fp16.h>
#include <cstdint>

#define NTOK 8192
#define INDIM 256
#define DIM 128
#define QKSCALE 0.08838834764831845f
#define FA_NSPLIT 2

// ---------------- device scratch ----------------
__device__ __half g_feath[NTOK * INDIM];
__device__ __half g_Wt[3 * DIM * INDIM];
__device__ __half g_Q[NTOK * DIM];                 // scaled by QKSCALE via Wq
__device__ __half g_K[NTOK * DIM];
__device__ __half g_Vt[136 * NTOK];                // V1^T [136][8192]
__device__ __half g_CVt[136 * NTOK];               // (C@V1)^T [136][8192]
__device__ float  g_scr[FA_NSPLIT * NTOK * 144];   // fa split partials [s][m][144]

// ---------------- helpers ----------------
__device__ __forceinline__ unsigned smem_u32(const void* p) {
    return static_cast<unsigned>(__cvta_generic_to_shared(p));
}
__device__ __forceinline__ float elu1(float x) { return x > 0.f ? x : expm1f(x); }
__device__ __forceinline__ unsigned packh2(float a, float b) {
    __half2 h = __floats2half2_rn(a, b);
    return *reinterpret_cast<unsigned*>(&h);
}
__device__ __forceinline__ void mma16816(float* c, const unsigned* a, const unsigned* b) {
    asm volatile(
        "mma.sync.aligned.m16n8k16.row.col.f32.f16.f16.f32 "
        "{%0,%1,%2,%3}, {%4,%5,%6,%7}, {%8,%9}, {%0,%1,%2,%3};\n"
        : "+f"(c[0]), "+f"(c[1]), "+f"(c[2]), "+f"(c[3])
        : "r"(a[0]), "r"(a[1]), "r"(a[2]), "r"(a[3]), "r"(b[0]), "r"(b[1]));
}
__device__ __forceinline__ void ldsm4(unsigned& r0, unsigned& r1, unsigned& r2, unsigned& r3,
                                      const void* p) {
    unsigned a = smem_u32(p);
    asm volatile("ldmatrix.sync.aligned.m8n8.x4.shared.b16 {%0,%1,%2,%3}, [%4];"
                 : "=r"(r0), "=r"(r1), "=r"(r2), "=r"(r3) : "r"(a));
}
__device__ __forceinline__ void ldsm2(unsigned& r0, unsigned& r1, const void* p) {
    unsigned a = smem_u32(p);
    asm volatile("ldmatrix.sync.aligned.m8n8.x2.shared.b16 {%0,%1}, [%2];"
                 : "=r"(r0), "=r"(r1) : "r"(a));
}
__device__ __forceinline__ void cpa16(void* smem_dst, const void* gsrc) {
    unsigned d = smem_u32(smem_dst);
    asm volatile("cp.async.cg.shared.global [%0], [%1], 16;" :: "r"(d), "l"(gsrc) : "memory");
}
#define CPCOMMIT() asm volatile("cp.async.commit_group;" ::: "memory")
#define CPWAIT0()  asm volatile("cp.async.wait_group 0;" ::: "memory")
#define CPWAIT1()  asm volatile("cp.async.wait_group 1;" ::: "memory")

// ---------------- prep kernels (2 launches so cv is launch #4 = profiled slot) ----------------
__global__ void prep_feat(const float* __restrict__ feat) {
    int i = blockIdx.x * blockDim.x + threadIdx.x;
    if (i < NTOK * INDIM) g_feath[i] = __float2half(feat[i]);
}
__global__ void prep_wv(const float* __restrict__ Wq, const float* __restrict__ Wk,
                        const float* __restrict__ Wv) {
    int i = blockIdx.x * blockDim.x + threadIdx.x;
    if (i < 3 * DIM * INDIM) {
        int x = i / (DIM * INDIM);
        int r = i % (DIM * INDIM);
        int n = r / INDIM, k = r % INDIM;
        const float* W = (x == 0) ? Wq : (x == 1) ? Wk : Wv;
        float v = W[k * DIM + n];
        if (x == 0) v *= QKSCALE;
        g_Wt[i] = __float2half(v);
    }
    if (i < 8 * NTOK) {   // Vt ones/pad rows 128..135
        int r = i / NTOK, m = i % NTOK;
        g_Vt[(size_t)(128 + r) * NTOK + m] = (r == 0) ? __float2half(1.0f) : __float2half(0.0f);
    }
}

// ---------------- QKV projection (z=2: smem transpose for coalesced Vt stores) ----------------
__global__ void qkv_kernel() {
    __shared__ __half SM[18432];                  // 36864 B: As | Bs, reused as T for z=2
    __half (*As)[72] = (__half(*)[72])SM;
    __half (*Bs)[72] = (__half(*)[72])(SM + 9216);
    const int tid = threadIdx.x, lane = tid & 31, warp = tid >> 5;
    const int wm = warp >> 1, wn = warp & 1;
    const int z = blockIdx.z;
    const int bm = blockIdx.x * 128;
    const __half* Bg = g_Wt + (size_t)z * DIM * INDIM;

    float acc[2][8][4];
#pragma unroll
    for (int mf = 0; mf < 2; mf++)
#pragma unroll
        for (int nf = 0; nf < 8; nf++)
#pragma unroll
            for (int i = 0; i < 4; i++) acc[mf][nf][i] = 0.f;

    for (int kt = 0; kt < INDIM; kt += 64) {
#pragma unroll
        for (int i = 0; i < 4; i++) {
            int idx = tid + i * 256, r = idx >> 3, c = idx & 7;
            *(uint4*)&As[r][c * 8] = *(const uint4*)&g_feath[(size_t)(bm + r) * INDIM + kt + c * 8];
        }
#pragma unroll
        for (int i = 0; i < 4; i++) {
            int idx = tid + i * 256, r = idx >> 3, c = idx & 7;
            *(uint4*)&Bs[r][c * 8] = *(const uint4*)&Bg[(size_t)r * INDIM + kt + c * 8];
        }
        __syncthreads();
        const int q = (lane & 3) * 2;
#pragma unroll
        for (int kk = 0; kk < 64; kk += 16) {
            unsigned a[2][4];
#pragma unroll
            for (int mf = 0; mf < 2; mf++) {
                int r = wm * 32 + mf * 16 + (lane >> 2);
                a[mf][0] = *(const unsigned*)&As[r][kk + q];
                a[mf][1] = *(const unsigned*)&As[r + 8][kk + q];
                a[mf][2] = *(const unsigned*)&As[r][kk + 8 + q];
                a[mf][3] = *(const unsigned*)&As[r + 8][kk + 8 + q];
            }
#pragma unroll
            for (int nf = 0; nf < 8; nf++) {
                int n = wn * 64 + nf * 8 + (lane >> 2);
                unsigned b[2];
                b[0] = *(const unsigned*)&Bs[n][kk + q];
                b[1] = *(const unsigned*)&Bs[n][kk + 8 + q];
                mma16816(acc[0][nf], a[0], b);
                mma16816(acc[1][nf], a[1], b);
            }
        }
        __syncthreads();
    }
    if (z == 2) {
        // transpose via smem: T[d][m_local], row stride 136 halves; 128*136=17408 <= 18432
        __half* T = SM;
#pragma unroll
        for (int mf = 0; mf < 2; mf++) {
            int rl = wm * 32 + mf * 16 + (lane >> 2);
#pragma unroll
            for (int nf = 0; nf < 8; nf++) {
                int c0 = wn * 64 + nf * 8 + (lane & 3) * 2;
                T[(size_t)c0 * 136 + rl]           = __float2half(acc[mf][nf][0]);
                T[(size_t)(c0 + 1) * 136 + rl]     = __float2half(acc[mf][nf][1]);
                T[(size_t)c0 * 136 + rl + 8]       = __float2half(acc[mf][nf][2]);
                T[(size_t)(c0 + 1) * 136 + rl + 8] = __float2half(acc[mf][nf][3]);
            }
        }
        __syncthreads();
        for (int idx = tid; idx < 128 * 16; idx += 256) {
            int d = idx >> 4, c8 = (idx & 15) * 8;
            *(uint4*)&g_Vt[(size_t)d * NTOK + bm + c8] = *(uint4*)&T[(size_t)d * 136 + c8];
        }
    } else {
#pragma unroll
        for (int mf = 0; mf < 2; mf++) {
            int r0 = bm + wm * 32 + mf * 16 + (lane >> 2);
#pragma unroll
            for (int nf = 0; nf < 8; nf++) {
                int c0 = wn * 64 + nf * 8 + (lane & 3) * 2;
                __half* O = (z == 0) ? g_Q : g_K;
                *(__half2*)&O[(size_t)r0 * DIM + c0] =
                    __floats2half2_rn(acc[mf][nf][0], acc[mf][nf][1]);
                *(__half2*)&O[(size_t)(r0 + 8) * DIM + c0] =
                    __floats2half2_rn(acc[mf][nf][2], acc[mf][nf][3]);
            }
        }
    }
}

// n-slice tables for cv's 2m x 4n warp grid over N=136
__device__ __constant__ int c_noff[4] = {0, 40, 72, 104};

// ---------------- cv: CVt = (C @ V1)^T, BM=64 (R8 core) + depth-2 Vt pipeline ----------------
// smem: Cs [64][272B] @0 (17408) | Vs 3x [136][272B] @17408,54400,91392. Total 128384.
__global__ void __launch_bounds__(256) cv_kernel(const float* __restrict__ Cg) {
    extern __shared__ char sm[];
    char* Cs = sm;
    char* Vs[3] = {sm + 17408, sm + 54400, sm + 91392};
    const int tid = threadIdx.x, lane = tid & 31, w = tid >> 5;
    const int mi = w >> 2, ni = w & 3;
    const int bm = blockIdx.x * 64;
    const int noff = c_noff[ni];
    const int nfr = (ni == 0) ? 5 : 4;

    const int rA = ((lane >> 3) & 1) * 8 + (lane & 7);
    const int cA = ((lane >> 4) & 1) * 8;
    const int rB = ((lane >> 4) & 1) * 8 + (lane & 7);
    const int cB = ((lane >> 3) & 1) * 8;
    const int rB2 = lane & 7;
    const int cB2 = ((lane >> 3) & 1) * 8;

    float acc[2][5][4];
#pragma unroll
    for (int mf = 0; mf < 2; mf++)
#pragma unroll
        for (int nf = 0; nf < 5; nf++)
#pragma unroll
            for (int i = 0; i < 4; i++) acc[mf][nf][i] = 0.f;

    // full-coverage 1-deep C register prefetch (R8 proven): 64 rows x 32 float4
    float4 pa[8];
#pragma unroll
    for (int i = 0; i < 8; i++) {
        int idx = tid + i * 256, r = idx >> 5, c4 = (idx & 31) * 4;
        pa[i] = *(const float4*)&Cg[(size_t)(bm + r) * NTOK + c4];
    }
    // depth-2 Vt cp.async: issue Vt(0), Vt(1) as separate groups
#pragma unroll
    for (int s = 0; s < 2; s++) {
#pragma unroll
        for (int i = 0; i < 9; i++) {
            int idx = tid + i * 256;
            if (idx < 2176) {
                int r = idx >> 4, c = idx & 15;
                cpa16(Vs[s] + r * 272 + c * 16, &g_Vt[(size_t)r * NTOK + s * 128 + c * 8]);
            }
        }
        CPCOMMIT();
    }

    for (int j = 0; j < 64; j++) {
        CPWAIT1();           // groups 0..j done => Vt(j) resident; Vt(j+1) may be in flight
        __syncthreads();     // compute(j-1) done: safe to overwrite Cs
        // issue Vt(j+2) into the buffer freed by compute(j-1); always commit (uniform accounting)
        if (j + 2 < 64) {
            int jb = (j + 2) * 128;
#pragma unroll
            for (int i = 0; i < 9; i++) {
                int idx = tid + i * 256;
                if (idx < 2176) {
                    int r = idx >> 4, c = idx & 15;
                    cpa16(Vs[(j + 2) % 3] + r * 272 + c * 16,
                          &g_Vt[(size_t)r * NTOK + jb + c * 8]);
                }
            }
        }
        CPCOMMIT();
        // store C regs(j) -> Cs (fp16)
#pragma unroll
        for (int i = 0; i < 8; i++) {
            int idx = tid + i * 256, r = idx >> 5, c4 = (idx & 31) * 4;
            uint2 v;
            v.x = packh2(pa[i].x, pa[i].y);
            v.y = packh2(pa[i].z, pa[i].w);
            *(uint2*)(Cs + r * 272 + c4 * 2) = v;
        }
        // prefetch C(j+1)
        if (j + 1 < 64) {
            int jb = (j + 1) * 128;
#pragma unroll
            for (int i = 0; i < 8; i++) {
                int idx = tid + i * 256, r = idx >> 5, c4 = (idx & 31) * 4;
                pa[i] = *(const float4*)&Cg[(size_t)(bm + r) * NTOK + jb + c4];
            }
        }
        __syncthreads();     // Cs(j) ready
        char* Vb = Vs[j % 3];
#pragma unroll
        for (int kk = 0; kk < 8; kk++) {
            unsigned A0[4], A1[4];
            ldsm4(A0[0], A0[1], A0[2], A0[3], Cs + (mi * 32 + rA) * 272 + (kk * 16 + cA) * 2);
            ldsm4(A1[0], A1[1], A1[2], A1[3], Cs + (mi * 32 + 16 + rA) * 272 + (kk * 16 + cA) * 2);
#pragma unroll
            for (int p = 0; p < 2; p++) {
                unsigned bb[4];
                ldsm4(bb[0], bb[1], bb[2], bb[3],
                      Vb + (noff + p * 16 + rB) * 272 + (kk * 16 + cB) * 2);
                mma16816(acc[0][p * 2], A0, bb);
                mma16816(acc[0][p * 2 + 1], A0, bb + 2);
                mma16816(acc[1][p * 2], A1, bb);
                mma16816(acc[1][p * 2 + 1], A1, bb + 2);
            }
            if (ni == 0) {
                unsigned b2[2];
                ldsm2(b2[0], b2[1], Vb + (32 + rB2) * 272 + (kk * 16 + cB2) * 2);
                mma16816(acc[0][4], A0, b2);
                mma16816(acc[1][4], A1, b2);
            }
        }
    }
    __syncthreads();
    __half* T = (__half*)Vs[0];
#pragma unroll
    for (int mf = 0; mf < 2; mf++) {
        int r = mi * 32 + mf * 16 + (lane >> 2);
        for (int nf = 0; nf < nfr; nf++) {
            int c = noff + nf * 8 + (lane & 3) * 2;
            T[c * 72 + r]           = __float2half(acc[mf][nf][0]);
            T[(c + 1) * 72 + r]     = __float2half(acc[mf][nf][1]);
            T[c * 72 + r + 8]       = __float2half(acc[mf][nf][2]);
            T[(c + 1) * 72 + r + 8] = __float2half(acc[mf][nf][3]);
        }
    }
    __syncthreads();
    for (int idx = tid; idx < 136 * 8; idx += 256) {
        int d = idx >> 3, c8 = (idx & 7) * 8;
        *(uint4*)&g_CVt[(size_t)d * NTOK + bm + c8] = *(uint4*)&T[d * 72 + c8];
    }
}

// ---------------- fused attention: register-resident P (exact R8 form) ----------------
__global__ void __launch_bounds__(128) fa_kernel() {
    extern __shared__ char sm[];
    char* Ks[2] = {sm, sm + 17408};
    char* CVs[2] = {sm + 34816, sm + 54400};
    const int tid = threadIdx.x, lane = tid & 31, w = tid >> 5;
    const int bm = blockIdx.x * 64;
    const int jbase = blockIdx.y * (NTOK / FA_NSPLIT);
    const int NIT = (NTOK / FA_NSPLIT) / 64;

    const int rA = ((lane >> 3) & 1) * 8 + (lane & 7);
    const int cA = ((lane >> 4) & 1) * 8;
    const int rB = ((lane >> 4) & 1) * 8 + (lane & 7);
    const int cB = ((lane >> 3) & 1) * 8;
    const int rB2 = lane & 7;
    const int cB2 = ((lane >> 3) & 1) * 8;

#pragma unroll
    for (int i = 0; i < 8; i++) {
        int idx = tid + i * 128, r = idx >> 4, c = idx & 15;
        *(uint4*)(Ks[0] + r * 272 + c * 16) = *(const uint4*)&g_Q[(size_t)(bm + r) * DIM + c * 8];
    }
    __syncthreads();
    unsigned aq[8][4];
#pragma unroll
    for (int kf = 0; kf < 8; kf++)
        ldsm4(aq[kf][0], aq[kf][1], aq[kf][2], aq[kf][3],
              Ks[0] + (w * 16 + rA) * 272 + (kf * 16 + cA) * 2);
    __syncthreads();

#pragma unroll
    for (int i = 0; i < 8; i++) {
        int idx = tid + i * 128, r = idx >> 4, c = idx & 15;
        cpa16(Ks[0] + r * 272 + c * 16, &g_K[(size_t)(jbase + r) * DIM + c * 8]);
    }
#pragma unroll
    for (int i = 0; i < 9; i++) {
        int idx = tid + i * 128;
        if (idx < 136 * 8) {
            int r = idx >> 3, c = idx & 7;
            cpa16(CVs[0] + r * 144 + c * 16, &g_CVt[(size_t)r * NTOK + jbase + c * 8]);
        }
    }
    CPCOMMIT();

    float acc[17][4];
#pragma unroll
    for (int nf = 0; nf < 17; nf++)
#pragma unroll
        for (int i = 0; i < 4; i++) acc[nf][i] = 0.f;

    for (int j = 0; j < NIT; j++) {
        int b = j & 1;
        CPWAIT0();
        __syncthreads();
        if (j + 1 < NIT) {
            int jb = jbase + (j + 1) * 64;
            char* kb = Ks[b ^ 1];
            char* cv = CVs[b ^ 1];
#pragma unroll
            for (int i = 0; i < 8; i++) {
                int idx = tid + i * 128, r = idx >> 4, c = idx & 15;
                cpa16(kb + r * 272 + c * 16, &g_K[(size_t)(jb + r) * DIM + c * 8]);
            }
#pragma unroll
            for (int i = 0; i < 9; i++) {
                int idx = tid + i * 128;
                if (idx < 136 * 8) {
                    int r = idx >> 3, c = idx & 7;
                    cpa16(cv + r * 144 + c * 16, &g_CVt[(size_t)r * NTOK + jb + c * 8]);
                }
            }
            CPCOMMIT();
        }
        float sacc[8][4];
#pragma unroll
        for (int g = 0; g < 8; g++)
#pragma unroll
            for (int i = 0; i < 4; i++) sacc[g][i] = 0.f;
#pragma unroll
        for (int kk = 0; kk < 8; kk++) {
#pragma unroll
            for (int g = 0; g < 4; g++) {
                unsigned bb[4];
                ldsm4(bb[0], bb[1], bb[2], bb[3],
                      Ks[b] + (g * 16 + rB) * 272 + (kk * 16 + cB) * 2);
                mma16816(sacc[2 * g], aq[kk], bb);
                mma16816(sacc[2 * g + 1], aq[kk], bb + 2);
            }
        }
        unsigned P[4][4];
#pragma unroll
        for (int kf = 0; kf < 4; kf++) {
            P[kf][0] = packh2(__expf(sacc[2 * kf][0]), __expf(sacc[2 * kf][1]));
            P[kf][1] = packh2(__expf(sacc[2 * kf][2]), __expf(sacc[2 * kf][3]));
            P[kf][2] = packh2(__expf(sacc[2 * kf + 1][0]), __expf(sacc[2 * kf + 1][1]));
            P[kf][3] = packh2(__expf(sacc[2 * kf + 1][2]), __expf(sacc[2 * kf + 1][3]));
        }
#pragma unroll
        for (int kk = 0; kk < 4; kk++) {
#pragma unroll
            for (int p = 0; p < 8; p++) {
                unsigned bb[4];
                ldsm4(bb[0], bb[1], bb[2], bb[3],
                      CVs[b] + (p * 16 + rB) * 144 + (kk * 16 + cB) * 2);
                mma16816(acc[2 * p], P[kk], bb);
                mma16816(acc[2 * p + 1], P[kk], bb + 2);
            }
            unsigned b2[2];
            ldsm2(b2[0], b2[1], CVs[b] + (128 + rB2) * 144 + (kk * 16 + cB2) * 2);
            mma16816(acc[16], P[kk], b2);
        }
    }
    {
        int row = bm + w * 16 + (lane >> 2);
        size_t base = ((size_t)blockIdx.y * NTOK + row) * 144;
#pragma unroll
        for (int nf = 0; nf < 17; nf++) {
            int c = nf * 8 + (lane & 3) * 2;
            *(float2*)&g_scr[base + c]           = make_float2(acc[nf][0], acc[nf][1]);
            *(float2*)&g_scr[base + 8 * 144 + c] = make_float2(acc[nf][2], acc[nf][3]);
        }
    }
}

// ---------------- final reduce ----------------
__global__ void fareduce_kernel(float* __restrict__ out) {
    int m = blockIdx.x;
    int d = threadIdx.x;
    float num = 0.f, den = 0.f;
#pragma unroll
    for (int s = 0; s < FA_NSPLIT; s++) {
        size_t b = ((size_t)s * NTOK + m) * 144;
        num += g_scr[b + d];
        den += g_scr[b + 128];
    }
    out[(size_t)m * DIM + d] = elu1(num / (den + 1e-9f));
}

// ---------------- launch ----------------
extern "C" void kernel_launch(void* const* d_in, const int* in_sizes, int n_in,
                              void* d_out, int out_size) {
    const float* feat = (const float*)d_in[0];
    const float* Cg   = (const float*)d_in[2];
    const float* Wq   = (const float*)d_in[3];
    const float* Wk   = (const float*)d_in[4];
    const float* Wv   = (const float*)d_in[5];
    float* out = (float*)d_out;

    cudaFuncSetAttribute(cv_kernel, cudaFuncAttributeMaxDynamicSharedMemorySize, 128384);
    cudaFuncSetAttribute(fa_kernel, cudaFuncAttributeMaxDynamicSharedMemorySize, 73984);

    // launch order: cv_kernel is the 4th launch = ncu-profiled slot
    prep_feat<<<(NTOK * INDIM + 255) / 256, 256>>>(feat);
    prep_wv<<<(3 * DIM * INDIM + 255) / 256, 256>>>(Wq, Wk, Wv);
    qkv_kernel<<<dim3(NTOK / 128, 1, 3), 256>>>();
    cv_kernel<<<NTOK / 64, 256, 128384>>>(Cg);
    fa_kernel<<<dim3(NTOK / 64, FA_NSPLIT), 128, 73984>>>();
    fareduce_kernel<<<NTOK, DIM>>>(out);
}

// round 17
// speedup vs baseline: 1.1662x; 1.1662x over previous
#include <cuda_runtime.h>
#include <cuda_fp16.h>
#include <cstdint>

#define NTOK 8192
#define INDIM 256
#define DIM 128
#define QKSCALE 0.08838834764831845f
#define FA_NSPLIT 3
#define FA_SPLIT_IT 43   // iters of 64 keys for splits 0,1; split 2 gets 42

// ---------------- device scratch ----------------
__device__ __half g_feath[NTOK * INDIM];
__device__ __half g_Wt[3 * DIM * INDIM];
__device__ __half g_Q[NTOK * DIM];                 // scaled by QKSCALE via Wq
__device__ __half g_K[NTOK * DIM];
__device__ __half g_Vt[136 * NTOK];                // V1^T [136][8192]
__device__ __half g_CVt[136 * NTOK];               // (C@V1)^T [136][8192]
__device__ float  g_scr[FA_NSPLIT * NTOK * 144];   // fa split partials [s][m][144]

// ---------------- helpers ----------------
__device__ __forceinline__ unsigned smem_u32(const void* p) {
    return static_cast<unsigned>(__cvta_generic_to_shared(p));
}
__device__ __forceinline__ float elu1(float x) { return x > 0.f ? x : expm1f(x); }
__device__ __forceinline__ unsigned packh2(float a, float b) {
    __half2 h = __floats2half2_rn(a, b);
    return *reinterpret_cast<unsigned*>(&h);
}
__device__ __forceinline__ void mma16816(float* c, const unsigned* a, const unsigned* b) {
    asm volatile(
        "mma.sync.aligned.m16n8k16.row.col.f32.f16.f16.f32 "
        "{%0,%1,%2,%3}, {%4,%5,%6,%7}, {%8,%9}, {%0,%1,%2,%3};\n"
        : "+f"(c[0]), "+f"(c[1]), "+f"(c[2]), "+f"(c[3])
        : "r"(a[0]), "r"(a[1]), "r"(a[2]), "r"(a[3]), "r"(b[0]), "r"(b[1]));
}
__device__ __forceinline__ void ldsm4(unsigned& r0, unsigned& r1, unsigned& r2, unsigned& r3,
                                      const void* p) {
    unsigned a = smem_u32(p);
    asm volatile("ldmatrix.sync.aligned.m8n8.x4.shared.b16 {%0,%1,%2,%3}, [%4];"
                 : "=r"(r0), "=r"(r1), "=r"(r2), "=r"(r3) : "r"(a));
}
__device__ __forceinline__ void ldsm2(unsigned& r0, unsigned& r1, const void* p) {
    unsigned a = smem_u32(p);
    asm volatile("ldmatrix.sync.aligned.m8n8.x2.shared.b16 {%0,%1}, [%2];"
                 : "=r"(r0), "=r"(r1) : "r"(a));
}
__device__ __forceinline__ void cpa16(void* smem_dst, const void* gsrc) {
    unsigned d = smem_u32(smem_dst);
    asm volatile("cp.async.cg.shared.global [%0], [%1], 16;" :: "r"(d), "l"(gsrc) : "memory");
}
#define CPCOMMIT() asm volatile("cp.async.commit_group;" ::: "memory")
#define CPWAIT0()  asm volatile("cp.async.wait_group 0;" ::: "memory")

// ---------------- merged prep (1 launch so fa lands in the profiled slot) ----------------
__global__ void prep_all(const float* __restrict__ feat, const float* __restrict__ Wq,
                         const float* __restrict__ Wk, const float* __restrict__ Wv) {
    int i = blockIdx.x * blockDim.x + threadIdx.x;
    if (i < NTOK * INDIM) g_feath[i] = __float2half(feat[i]);
    if (i < 3 * DIM * INDIM) {
        int x = i / (DIM * INDIM);
        int r = i % (DIM * INDIM);
        int n = r / INDIM, k = r % INDIM;
        const float* W = (x == 0) ? Wq : (x == 1) ? Wk : Wv;
        float v = W[k * DIM + n];
        if (x == 0) v *= QKSCALE;
        g_Wt[i] = __float2half(v);
    }
    if (i < 8 * NTOK) {   // Vt ones/pad rows 128..135
        int r = i / NTOK, m = i % NTOK;
        g_Vt[(size_t)(128 + r) * NTOK + m] = (r == 0) ? __float2half(1.0f) : __float2half(0.0f);
    }
}

// ---------------- QKV projection (exact R8 form) ----------------
__global__ void qkv_kernel() {
    __shared__ __half As[128][72];
    __shared__ __half Bs[128][72];
    const int tid = threadIdx.x, lane = tid & 31, warp = tid >> 5;
    const int wm = warp >> 1, wn = warp & 1;
    const int z = blockIdx.z;
    const int bm = blockIdx.x * 128;
    const __half* Bg = g_Wt + (size_t)z * DIM * INDIM;

    float acc[2][8][4];
#pragma unroll
    for (int mf = 0; mf < 2; mf++)
#pragma unroll
        for (int nf = 0; nf < 8; nf++)
#pragma unroll
            for (int i = 0; i < 4; i++) acc[mf][nf][i] = 0.f;

    for (int kt = 0; kt < INDIM; kt += 64) {
#pragma unroll
        for (int i = 0; i < 4; i++) {
            int idx = tid + i * 256, r = idx >> 3, c = idx & 7;
            *(uint4*)&As[r][c * 8] = *(const uint4*)&g_feath[(size_t)(bm + r) * INDIM + kt + c * 8];
        }
#pragma unroll
        for (int i = 0; i < 4; i++) {
            int idx = tid + i * 256, r = idx >> 3, c = idx & 7;
            *(uint4*)&Bs[r][c * 8] = *(const uint4*)&Bg[(size_t)r * INDIM + kt + c * 8];
        }
        __syncthreads();
        const int q = (lane & 3) * 2;
#pragma unroll
        for (int kk = 0; kk < 64; kk += 16) {
            unsigned a[2][4];
#pragma unroll
            for (int mf = 0; mf < 2; mf++) {
                int r = wm * 32 + mf * 16 + (lane >> 2);
                a[mf][0] = *(const unsigned*)&As[r][kk + q];
                a[mf][1] = *(const unsigned*)&As[r + 8][kk + q];
                a[mf][2] = *(const unsigned*)&As[r][kk + 8 + q];
                a[mf][3] = *(const unsigned*)&As[r + 8][kk + 8 + q];
            }
#pragma unroll
            for (int nf = 0; nf < 8; nf++) {
                int n = wn * 64 + nf * 8 + (lane >> 2);
                unsigned b[2];
                b[0] = *(const unsigned*)&Bs[n][kk + q];
                b[1] = *(const unsigned*)&Bs[n][kk + 8 + q];
                mma16816(acc[0][nf], a[0], b);
                mma16816(acc[1][nf], a[1], b);
            }
        }
        __syncthreads();
    }
#pragma unroll
    for (int mf = 0; mf < 2; mf++) {
        int r0 = bm + wm * 32 + mf * 16 + (lane >> 2);
#pragma unroll
        for (int nf = 0; nf < 8; nf++) {
            int c0 = wn * 64 + nf * 8 + (lane & 3) * 2;
            if (z == 2) {
                g_Vt[(size_t)c0 * NTOK + r0]           = __float2half(acc[mf][nf][0]);
                g_Vt[(size_t)(c0 + 1) * NTOK + r0]     = __float2half(acc[mf][nf][1]);
                g_Vt[(size_t)c0 * NTOK + r0 + 8]       = __float2half(acc[mf][nf][2]);
                g_Vt[(size_t)(c0 + 1) * NTOK + r0 + 8] = __float2half(acc[mf][nf][3]);
            } else {
                __half* O = (z == 0) ? g_Q : g_K;
                *(__half2*)&O[(size_t)r0 * DIM + c0] =
                    __floats2half2_rn(acc[mf][nf][0], acc[mf][nf][1]);
                *(__half2*)&O[(size_t)(r0 + 8) * DIM + c0] =
                    __floats2half2_rn(acc[mf][nf][2], acc[mf][nf][3]);
            }
        }
    }
}

// n-slice tables for cv's 2m x 4n warp grid over N=136
__device__ __constant__ int c_noff[4] = {0, 40, 72, 104};

// ---------------- cv: CVt = (C @ V1)^T, full-K per CTA (exact R8 form) ----------------
__global__ void __launch_bounds__(256) cv_kernel(const float* __restrict__ Cg) {
    extern __shared__ char sm[];
    char* Cs = sm;
    char* Vs[2] = {sm + 17408, sm + 54400};
    const int tid = threadIdx.x, lane = tid & 31, w = tid >> 5;
    const int mi = w >> 2, ni = w & 3;
    const int bm = blockIdx.x * 64;
    const int noff = c_noff[ni];
    const int nfr = (ni == 0) ? 5 : 4;

    const int rA = ((lane >> 3) & 1) * 8 + (lane & 7);
    const int cA = ((lane >> 4) & 1) * 8;
    const int rB = ((lane >> 4) & 1) * 8 + (lane & 7);
    const int cB = ((lane >> 3) & 1) * 8;
    const int rB2 = lane & 7;
    const int cB2 = ((lane >> 3) & 1) * 8;

    float acc[2][5][4];
#pragma unroll
    for (int mf = 0; mf < 2; mf++)
#pragma unroll
        for (int nf = 0; nf < 5; nf++)
#pragma unroll
            for (int i = 0; i < 4; i++) acc[mf][nf][i] = 0.f;

    float4 pa[8];
#pragma unroll
    for (int i = 0; i < 8; i++) {
        int idx = tid + i * 256, r = idx >> 5, c4 = (idx & 31) * 4;
        pa[i] = *(const float4*)&Cg[(size_t)(bm + r) * NTOK + c4];
    }
#pragma unroll
    for (int i = 0; i < 9; i++) {
        int idx = tid + i * 256;
        if (idx < 2176) {
            int r = idx >> 4, c = idx & 15;
            cpa16(Vs[0] + r * 272 + c * 16, &g_Vt[(size_t)r * NTOK + c * 8]);
        }
    }
    CPCOMMIT();

    for (int j = 0; j < 64; j++) {
        int b = j & 1;
        CPWAIT0();
        __syncthreads();
        if (j + 1 < 64) {
            int jb = (j + 1) * 128;
#pragma unroll
            for (int i = 0; i < 9; i++) {
                int idx = tid + i * 256;
                if (idx < 2176) {
                    int r = idx >> 4, c = idx & 15;
                    cpa16(Vs[b ^ 1] + r * 272 + c * 16, &g_Vt[(size_t)r * NTOK + jb + c * 8]);
                }
            }
            CPCOMMIT();
        }
#pragma unroll
        for (int i = 0; i < 8; i++) {
            int idx = tid + i * 256, r = idx >> 5, c4 = (idx & 31) * 4;
            uint2 v;
            v.x = packh2(pa[i].x, pa[i].y);
            v.y = packh2(pa[i].z, pa[i].w);
            *(uint2*)(Cs + r * 272 + c4 * 2) = v;
        }
        if (j + 1 < 64) {
            int jb = (j + 1) * 128;
#pragma unroll
            for (int i = 0; i < 8; i++) {
                int idx = tid + i * 256, r = idx >> 5, c4 = (idx & 31) * 4;
                pa[i] = *(const float4*)&Cg[(size_t)(bm + r) * NTOK + jb + c4];
            }
        }
        __syncthreads();
#pragma unroll
        for (int kk = 0; kk < 8; kk++) {
            unsigned A0[4], A1[4];
            ldsm4(A0[0], A0[1], A0[2], A0[3], Cs + (mi * 32 + rA) * 272 + (kk * 16 + cA) * 2);
            ldsm4(A1[0], A1[1], A1[2], A1[3], Cs + (mi * 32 + 16 + rA) * 272 + (kk * 16 + cA) * 2);
#pragma unroll
            for (int p = 0; p < 2; p++) {
                unsigned bb[4];
                ldsm4(bb[0], bb[1], bb[2], bb[3],
                      Vs[b] + (noff + p * 16 + rB) * 272 + (kk * 16 + cB) * 2);
                mma16816(acc[0][p * 2], A0, bb);
                mma16816(acc[0][p * 2 + 1], A0, bb + 2);
                mma16816(acc[1][p * 2], A1, bb);
                mma16816(acc[1][p * 2 + 1], A1, bb + 2);
            }
            if (ni == 0) {
                unsigned b2[2];
                ldsm2(b2[0], b2[1], Vs[b] + (32 + rB2) * 272 + (kk * 16 + cB2) * 2);
                mma16816(acc[0][4], A0, b2);
                mma16816(acc[1][4], A1, b2);
            }
        }
    }
    __syncthreads();
    __half* T = (__half*)Vs[0];
#pragma unroll
    for (int mf = 0; mf < 2; mf++) {
        int r = mi * 32 + mf * 16 + (lane >> 2);
        for (int nf = 0; nf < nfr; nf++) {
            int c = noff + nf * 8 + (lane & 3) * 2;
            T[c * 72 + r]           = __float2half(acc[mf][nf][0]);
            T[(c + 1) * 72 + r]     = __float2half(acc[mf][nf][1]);
            T[c * 72 + r + 8]       = __float2half(acc[mf][nf][2]);
            T[(c + 1) * 72 + r + 8] = __float2half(acc[mf][nf][3]);
        }
    }
    __syncthreads();
    for (int idx = tid; idx < 136 * 8; idx += 256) {
        int d = idx >> 3, c8 = (idx & 7) * 8;
        *(uint4*)&g_CVt[(size_t)d * NTOK + bm + c8] = *(uint4*)&T[d * 72 + c8];
    }
}

// ---------------- fused attention: register-resident P, NSPLIT=3 (single wave, 2.6 CTA/SM) ----------------
__global__ void __launch_bounds__(128) fa_kernel() {
    extern __shared__ char sm[];
    char* Ks[2] = {sm, sm + 17408};
    char* CVs[2] = {sm + 34816, sm + 54400};
    const int tid = threadIdx.x, lane = tid & 31, w = tid >> 5;
    const int bm = blockIdx.x * 64;
    const int jbase = blockIdx.y * (FA_SPLIT_IT * 64);
    const int NIT = (blockIdx.y < FA_NSPLIT - 1) ? FA_SPLIT_IT : (128 - FA_SPLIT_IT * (FA_NSPLIT - 1));

    const int rA = ((lane >> 3) & 1) * 8 + (lane & 7);
    const int cA = ((lane >> 4) & 1) * 8;
    const int rB = ((lane >> 4) & 1) * 8 + (lane & 7);
    const int cB = ((lane >> 3) & 1) * 8;
    const int rB2 = lane & 7;
    const int cB2 = ((lane >> 3) & 1) * 8;

#pragma unroll
    for (int i = 0; i < 8; i++) {
        int idx = tid + i * 128, r = idx >> 4, c = idx & 15;
        *(uint4*)(Ks[0] + r * 272 + c * 16) = *(const uint4*)&g_Q[(size_t)(bm + r) * DIM + c * 8];
    }
    __syncthreads();
    unsigned aq[8][4];
#pragma unroll
    for (int kf = 0; kf < 8; kf++)
        ldsm4(aq[kf][0], aq[kf][1], aq[kf][2], aq[kf][3],
              Ks[0] + (w * 16 + rA) * 272 + (kf * 16 + cA) * 2);
    __syncthreads();

#pragma unroll
    for (int i = 0; i < 8; i++) {
        int idx = tid + i * 128, r = idx >> 4, c = idx & 15;
        cpa16(Ks[0] + r * 272 + c * 16, &g_K[(size_t)(jbase + r) * DIM + c * 8]);
    }
#pragma unroll
    for (int i = 0; i < 9; i++) {
        int idx = tid + i * 128;
        if (idx < 136 * 8) {
            int r = idx >> 3, c = idx & 7;
            cpa16(CVs[0] + r * 144 + c * 16, &g_CVt[(size_t)r * NTOK + jbase + c * 8]);
        }
    }
    CPCOMMIT();

    float acc[17][4];
#pragma unroll
    for (int nf = 0; nf < 17; nf++)
#pragma unroll
        for (int i = 0; i < 4; i++) acc[nf][i] = 0.f;

    for (int j = 0; j < NIT; j++) {
        int b = j & 1;
        CPWAIT0();
        __syncthreads();
        if (j + 1 < NIT) {
            int jb = jbase + (j + 1) * 64;
            char* kb = Ks[b ^ 1];
            char* cv = CVs[b ^ 1];
#pragma unroll
            for (int i = 0; i < 8; i++) {
                int idx = tid + i * 128, r = idx >> 4, c = idx & 15;
                cpa16(kb + r * 272 + c * 16, &g_K[(size_t)(jb + r) * DIM + c * 8]);
            }
#pragma unroll
            for (int i = 0; i < 9; i++) {
                int idx = tid + i * 128;
                if (idx < 136 * 8) {
                    int r = idx >> 3, c = idx & 7;
                    cpa16(cv + r * 144 + c * 16, &g_CVt[(size_t)r * NTOK + jb + c * 8]);
                }
            }
            CPCOMMIT();
        }
        float sacc[8][4];
#pragma unroll
        for (int g = 0; g < 8; g++)
#pragma unroll
            for (int i = 0; i < 4; i++) sacc[g][i] = 0.f;
#pragma unroll
        for (int kk = 0; kk < 8; kk++) {
#pragma unroll
            for (int g = 0; g < 4; g++) {
                unsigned bb[4];
                ldsm4(bb[0], bb[1], bb[2], bb[3],
                      Ks[b] + (g * 16 + rB) * 272 + (kk * 16 + cB) * 2);
                mma16816(sacc[2 * g], aq[kk], bb);
                mma16816(sacc[2 * g + 1], aq[kk], bb + 2);
            }
        }
        unsigned P[4][4];
#pragma unroll
        for (int kf = 0; kf < 4; kf++) {
            P[kf][0] = packh2(__expf(sacc[2 * kf][0]), __expf(sacc[2 * kf][1]));
            P[kf][1] = packh2(__expf(sacc[2 * kf][2]), __expf(sacc[2 * kf][3]));
            P[kf][2] = packh2(__expf(sacc[2 * kf + 1][0]), __expf(sacc[2 * kf + 1][1]));
            P[kf][3] = packh2(__expf(sacc[2 * kf + 1][2]), __expf(sacc[2 * kf + 1][3]));
        }
#pragma unroll
        for (int kk = 0; kk < 4; kk++) {
#pragma unroll
            for (int p = 0; p < 8; p++) {
                unsigned bb[4];
                ldsm4(bb[0], bb[1], bb[2], bb[3],
                      CVs[b] + (p * 16 + rB) * 144 + (kk * 16 + cB) * 2);
                mma16816(acc[2 * p], P[kk], bb);
                mma16816(acc[2 * p + 1], P[kk], bb + 2);
            }
            unsigned b2[2];
            ldsm2(b2[0], b2[1], CVs[b] + (128 + rB2) * 144 + (kk * 16 + cB2) * 2);
            mma16816(acc[16], P[kk], b2);
        }
    }
    {
        int row = bm + w * 16 + (lane >> 2);
        size_t base = ((size_t)blockIdx.y * NTOK + row) * 144;
#pragma unroll
        for (int nf = 0; nf < 17; nf++) {
            int c = nf * 8 + (lane & 3) * 2;
            *(float2*)&g_scr[base + c]           = make_float2(acc[nf][0], acc[nf][1]);
            *(float2*)&g_scr[base + 8 * 144 + c] = make_float2(acc[nf][2], acc[nf][3]);
        }
    }
}

// ---------------- final reduce ----------------
__global__ void fareduce_kernel(float* __restrict__ out) {
    int m = blockIdx.x;
    int d = threadIdx.x;
    float num = 0.f, den = 0.f;
#pragma unroll
    for (int s = 0; s < FA_NSPLIT; s++) {
        size_t b = ((size_t)s * NTOK + m) * 144;
        num += g_scr[b + d];
        den += g_scr[b + 128];
    }
    out[(size_t)m * DIM + d] = elu1(num / (den + 1e-9f));
}

// ---------------- launch ----------------
extern "C" void kernel_launch(void* const* d_in, const int* in_sizes, int n_in,
                              void* d_out, int out_size) {
    const float* feat = (const float*)d_in[0];
    const float* Cg   = (const float*)d_in[2];
    const float* Wq   = (const float*)d_in[3];
    const float* Wk   = (const float*)d_in[4];
    const float* Wv   = (const float*)d_in[5];
    float* out = (float*)d_out;

    cudaFuncSetAttribute(cv_kernel, cudaFuncAttributeMaxDynamicSharedMemorySize, 91392);
    cudaFuncSetAttribute(fa_kernel, cudaFuncAttributeMaxDynamicSharedMemorySize, 73984);

    // launch order: fa_kernel is the 4th launch = ncu-profiled slot
    prep_all<<<(NTOK * INDIM + 255) / 256, 256>>>(feat, Wq, Wk, Wv);
    qkv_kernel<<<dim3(NTOK / 128, 1, 3), 256>>>();
    cv_kernel<<<NTOK / 64, 256, 91392>>>(Cg);
    fa_kernel<<<dim3(NTOK / 64, FA_NSPLIT), 128, 73984>>>();
    fareduce_kernel<<<NTOK, DIM>>>(out);
}